// round 12
// baseline (speedup 1.0000x reference)
#include <cuda_runtime.h>
#include <cuda_bf16.h>
#include <cstdint>

#define BSZ 4
#define CCH 256
#define HH 64
#define WW 64
#define HWN 4096
#define GG 4
#define CG 64

#define MP_STRIDE (BSZ*64*HWN)    // per mod1-partial buffer (floats)
#define OP_STRIDE (BSZ*72*HWN)    // per off2-partial buffer (floats)

// ---------------- warp-MMA helpers ----------------
__device__ __forceinline__ uint32_t smem_u32(const void* p){
  uint32_t a; asm("{ .reg .u64 t; cvta.to.shared.u64 t, %1; cvt.u32.u64 %0, t; }" : "=r"(a) : "l"(p)); return a;
}
__device__ __forceinline__ void ldsm_x4(uint32_t* r, uint32_t a) {
    asm volatile("ldmatrix.sync.aligned.m8n8.x4.shared.b16 {%0,%1,%2,%3}, [%4];"
        : "=r"(r[0]), "=r"(r[1]), "=r"(r[2]), "=r"(r[3]) : "r"(a));
}
__device__ __forceinline__ void ldsm_x2(uint32_t* r, uint32_t a) {
    asm volatile("ldmatrix.sync.aligned.m8n8.x2.shared.b16 {%0,%1}, [%2];"
        : "=r"(r[0]), "=r"(r[1]) : "r"(a));
}
__device__ __forceinline__ void mma_bf16(float* d, const uint32_t* a, uint32_t b0, uint32_t b1) {
    asm volatile("mma.sync.aligned.m16n8k16.row.col.f32.bf16.bf16.f32 "
        "{%0,%1,%2,%3}, {%4,%5,%6,%7}, {%8,%9}, {%0,%1,%2,%3};"
        : "+f"(d[0]), "+f"(d[1]), "+f"(d[2]), "+f"(d[3])
        : "r"(a[0]), "r"(a[1]), "r"(a[2]), "r"(a[3]), "r"(b0), "r"(b1));
}
__device__ __forceinline__ uint32_t pack_hl(float v) {
    __nv_bfloat16 h = __float2bfloat16(v);
    __nv_bfloat16 l = __float2bfloat16(v - __bfloat162float(h));
    return (uint32_t)__bfloat16_as_ushort(h) | ((uint32_t)__bfloat16_as_ushort(l) << 16);
}

// ---------------- scratch ----------------
__device__ uint32_t g_xP[BSZ * CCH * HWN];     // packed bf16 hi/lo of x2d
__device__ uint32_t g_hP[BSZ * CCH * HWN];     // packed off1 output (post-GELU)
__device__ float    g_mp[4 * MP_STRIDE];       // mod1 partials (pre-GELU)
__device__ float    g_op[4 * OP_STRIDE];       // off2 partials
__device__ float    g_mod[BSZ * 36 * HWN];     // mod2 out (post-sigmoid)

// prepacked bf16 hi/lo weights; per part: [chunk=cb*9+tap][rowsPad][32]
#define W_TOTAL 502272
__device__ __nv_bfloat16 g_wHi[W_TOTAL];
__device__ __nv_bfloat16 g_wLo[W_TOTAL];

// ---------------- transpose + bf16-split-pack ----------------
__global__ void transpose_kernel(const float* __restrict__ x, uint32_t* __restrict__ xP) {
    __shared__ float tile[32][33];
    int b  = blockIdx.z;
    int n0 = blockIdx.x * 32;
    int c0 = blockIdx.y * 32;
    int tx = threadIdx.x, ty = threadIdx.y;
    #pragma unroll
    for (int i = ty; i < 32; i += 8)
        tile[i][tx] = x[((size_t)b*HWN + n0 + i)*CCH + c0 + tx];
    __syncthreads();
    #pragma unroll
    for (int i = ty; i < 32; i += 8)
        xP[((size_t)b*CCH + c0 + i)*HWN + n0 + tx] = pack_hl(tile[tx][i]);
}

// ---------------- weight prepack (25 parts) ----------------
struct PackPart { const float* w; int dstBase, wCinG, nInW0, ciInW0, CoutValid, rowsPad; };
struct PackAll  { PackPart p[25]; };

__global__ void prepack_kernel(PackAll a) {
    long e = (long)blockIdx.x * 256 + threadIdx.x;
    int q = 0;
    for (; q < 25; q++) {
        long t = 18L * a.p[q].rowsPad * 32;
        if (e < t) break;
        e -= t;
    }
    if (q >= 25) return;
    PackPart pp = a.p[q];
    int e2 = (int)e;
    int chunk = e2 / (pp.rowsPad * 32);
    int r     = e2 - chunk * (pp.rowsPad * 32);
    int row = r >> 5, j = r & 31;
    int cb = chunk / 9, tap = chunk - cb * 9;
    float v = 0.f;
    if (row < pp.CoutValid)
        v = pp.w[(((size_t)(pp.nInW0 + row)) * pp.wCinG + pp.ciInW0 + cb * 32 + j) * 9 + tap];
    __nv_bfloat16 h = __float2bfloat16(v);
    long dst = pp.dstBase + e;
    g_wHi[dst] = h;
    g_wLo[dst] = __float2bfloat16(v - __bfloat162float(h));
}

// ---------------- implicit-GEMM conv via mma.sync ----------------
struct ConvPart {
    const void* in;
    long inStride; int nPart;
    int inPacked, inAct;
    const __nv_bfloat16 *wHi, *wLo;       // pre-offset to part base
    const float* bias;                     // pre-offset to coutBase
    void* out;
    int cinTotal, ciBase, coutTotal, coutBase, CoutValid, nCb, act, outPacked, addBias;
};
struct ConvArgs { ConvPart p[16]; };

#define SM_A_HI 0
#define SM_A_LO 21120
#define SM_B    42240

template<int NFR>
__device__ __forceinline__ void stage_b(char* smem, const __nv_bfloat16* wHi,
                                        const __nv_bfloat16* wLo, int chunk, int par, int tid) {
    constexpr int BBUF = NFR * 8 * 80;
    const int nv = NFR * 32;
    const uint4* sH = (const uint4*)(wHi + (size_t)chunk * (NFR * 8 * 32));
    const uint4* sL = (const uint4*)(wLo + (size_t)chunk * (NFR * 8 * 32));
    for (int i = tid; i < 2 * nv; i += 256) {
        int arr = (i >= nv);
        int ii  = arr ? i - nv : i;
        uint4 v = arr ? sL[ii] : sH[ii];
        int n = ii >> 2, qq = ii & 3;
        *(uint4*)(smem + SM_B + (size_t)(par * 2 + arr) * BBUF + n * 80 + qq * 16) = v;
    }
}

template<int NFR>
__global__ void __launch_bounds__(256, 4) conv_mma(ConvArgs args) {
    constexpr int BBUF = NFR * 8 * 80;
    extern __shared__ char smem[];
    const ConvPart P = args.p[blockIdx.y];
    const int tid = threadIdx.x;
    const int wid = tid >> 5, lid = tid & 31;
    const int b  = blockIdx.x >> 5;
    const int r0 = (blockIdx.x & 31) << 1;
    uint32_t sb = smem_u32(smem);

    float acc[NFR][4];
    #pragma unroll
    for (int i = 0; i < NFR; i++) { acc[i][0]=acc[i][1]=acc[i][2]=acc[i][3]=0.f; }

    const int m    = wid * 16 + (lid & 15);
    const int yloc = m >> 6, xpix = m & 63;
    const uint32_t aBase  = (uint32_t)(((yloc + 1) * 66 + (xpix + 1)) * 80) + ((lid >> 4) * 16);
    const int nloc4  = (lid & 7) + ((lid >> 4) << 3);
    const int khalfB = ((lid >> 3) & 1) * 16;

    #pragma unroll 1
    for (int cb = 0; cb < P.nCb; cb++) {
        __syncthreads();
        const size_t chBase = ((size_t)(b * P.cinTotal + P.ciBase + cb * 32)) * HWN;
        if (P.inPacked) {
            const uint32_t* ip = (const uint32_t*)P.in + chBase;
            #pragma unroll 1
            for (int i = tid; i < 4 * 66 * 32; i += 256) {
                int j   = i / 264;
                int pix = i - j * 264;
                int py = pix / 66, px = pix - py * 66;
                int y = r0 - 1 + py, x = px - 1;
                uint32_t w = 0;
                if ((unsigned)y < HH && (unsigned)x < WW) w = ip[(size_t)j * HWN + y * WW + x];
                uint32_t o = (uint32_t)(py * 66 + px) * 80 + j * 2;
                *(uint16_t*)(smem + SM_A_HI + o) = (uint16_t)w;
                *(uint16_t*)(smem + SM_A_LO + o) = (uint16_t)(w >> 16);
            }
        } else {
            const float* ip = (const float*)P.in + chBase;
            #pragma unroll 1
            for (int i = tid; i < 4 * 66 * 32; i += 256) {
                int j   = i / 264;
                int pix = i - j * 264;
                int py = pix / 66, px = pix - py * 66;
                int y = r0 - 1 + py, x = px - 1;
                float v = 0.f;
                if ((unsigned)y < HH && (unsigned)x < WW) {
                    size_t idx = (size_t)j * HWN + y * WW + x;
                    v = ip[idx];
                    for (int k = 1; k < P.nPart; k++) v += ip[idx + (size_t)k * P.inStride];
                    if (P.inAct) v = v * normcdff(v);
                }
                __nv_bfloat16 h = __float2bfloat16(v);
                __nv_bfloat16 l = __float2bfloat16(v - __bfloat162float(h));
                uint32_t o = (uint32_t)(py * 66 + px) * 80 + j * 2;
                *(__nv_bfloat16*)(smem + SM_A_HI + o) = h;
                *(__nv_bfloat16*)(smem + SM_A_LO + o) = l;
            }
        }
        stage_b<NFR>(smem, P.wHi, P.wLo, cb * 9, 0, tid);

        #pragma unroll 1
        for (int tap = 0; tap < 9; tap++) {
            __syncthreads();
            if (tap < 8) stage_b<NFR>(smem, P.wHi, P.wLo, cb * 9 + tap + 1, (tap + 1) & 1, tid);
            const int dy = tap / 3 - 1, dx = tap % 3 - 1;
            const uint32_t aOfs  = aBase + (dy * 66 + dx) * 80;
            const uint32_t bBase = sb + SM_B + (uint32_t)((tap & 1) * 2) * BBUF;
            #pragma unroll
            for (int k16 = 0; k16 < 2; k16++) {
                uint32_t ah[4], al[4];
                ldsm_x4(ah, sb + SM_A_HI + aOfs + k16 * 32);
                ldsm_x4(al, sb + SM_A_LO + aOfs + k16 * 32);
                #pragma unroll
                for (int nf2 = 0; nf2 < NFR / 2; nf2++) {
                    uint32_t bAddr = bBase + (uint32_t)(nf2 * 16 + nloc4) * 80 + k16 * 32 + khalfB;
                    uint32_t bh[4], bl[4];
                    ldsm_x4(bh, bAddr);
                    ldsm_x4(bl, bAddr + BBUF);
                    mma_bf16(acc[nf2*2],   ah, bh[0], bh[1]);
                    mma_bf16(acc[nf2*2+1], ah, bh[2], bh[3]);
                    mma_bf16(acc[nf2*2],   al, bh[0], bh[1]);
                    mma_bf16(acc[nf2*2+1], al, bh[2], bh[3]);
                    mma_bf16(acc[nf2*2],   ah, bl[0], bl[1]);
                    mma_bf16(acc[nf2*2+1], ah, bl[2], bl[3]);
                }
                if (NFR & 1) {
                    const int nf = NFR - 1;
                    uint32_t bAddr = bBase + (uint32_t)(nf * 8 + (lid & 7)) * 80 + k16 * 32 + khalfB;
                    uint32_t bh[2], bl[2];
                    ldsm_x2(bh, bAddr);
                    ldsm_x2(bl, bAddr + BBUF);
                    mma_bf16(acc[nf], ah, bh[0], bh[1]);
                    mma_bf16(acc[nf], al, bh[0], bh[1]);
                    mma_bf16(acc[nf], ah, bl[0], bl[1]);
                }
            }
        }
    }

    // epilogue via smem transpose for coalesced stores
    __syncthreads();
    float* sd = (float*)smem;
    {
        const int rr = lid >> 2, cc = (lid & 3) * 2;
        const int mB = wid * 16;
        #pragma unroll
        for (int nf = 0; nf < NFR; nf++) {
            int n = nf * 8 + cc;
            sd[(n    ) * 132 + mB + rr    ] = acc[nf][0];
            sd[(n + 1) * 132 + mB + rr    ] = acc[nf][1];
            sd[(n    ) * 132 + mB + rr + 8] = acc[nf][2];
            sd[(n + 1) * 132 + mB + rr + 8] = acc[nf][3];
        }
    }
    __syncthreads();
    const int pixBase = r0 * WW;
    for (int i = tid; i < P.CoutValid * 128; i += 256) {
        int n = i >> 7, mm = i & 127;
        float v = sd[n * 132 + mm] + (P.addBias ? P.bias[n] : 0.f);
        if (P.act == 1)      v = v * normcdff(v);
        else if (P.act == 2) v = 1.f / (1.f + expf(-v));
        size_t oidx = ((size_t)(b * P.coutTotal + P.coutBase + n)) * HWN + pixBase + mm;
        if (P.outPacked) ((uint32_t*)P.out)[oidx] = pack_hl(v);
        else             ((float*)P.out)[oidx] = v;
    }
}

// ---------------- deformable sampling (sums 4 off partials) ----------------
__global__ void __launch_bounds__(256) sample_kernel(
    const float* __restrict__ x,
    const float* __restrict__ op,
    const float* __restrict__ mod,
    float* __restrict__ out)
{
    __shared__ float4 sw[36];
    __shared__ int4   so[36];

    const int t    = threadIdx.x;
    const int c    = t & 63;
    const int pl   = t >> 6;
    const int pix0 = blockIdx.x * 4;
    const int g    = blockIdx.y;
    const int b    = blockIdx.z;

    if (t < 36) {
        const int pli = t / 9;
        const int p   = t - pli * 9;
        const int pix = pix0 + pli;
        const int yq  = pix >> 6;
        const int xq  = pix & 63;

        const float* offp = op  + ((size_t)b*72 + g*18)*HWN + pix;
        const float* modp = mod + ((size_t)b*36 + g*9 )*HWN + pix;

        float ox = 0.f, oy = 0.f;
        #pragma unroll
        for (int k = 0; k < 4; k++) {
            ox += offp[(size_t)k*OP_STRIDE + (size_t)p*HWN];
            oy += offp[(size_t)k*OP_STRIDE + (size_t)(9+p)*HWN];
        }
        float mv = modp[(size_t)p*HWN] * (1.f/9.f);

        float px = fminf(fmaxf((float)(xq + (p%3) - 1) + ox, 0.f), (float)(WW-1));
        float py = fminf(fmaxf((float)(yq + (p/3) - 1) + oy, 0.f), (float)(HH-1));

        float x0f = floorf(px), y0f = floorf(py);
        float wx = px - x0f, wy = py - y0f;
        int x0 = (int)x0f, y0 = (int)y0f;
        int x1 = min(x0 + 1, WW-1);
        int y1 = min(y0 + 1, HH-1);

        sw[t] = make_float4((1.f-wx)*(1.f-wy)*mv, wx*(1.f-wy)*mv,
                            (1.f-wx)*wy*mv,       wx*wy*mv);
        so[t] = make_int4((y0*WW + x0)*CCH, (y0*WW + x1)*CCH,
                          (y1*WW + x0)*CCH, (y1*WW + x1)*CCH);
    }
    __syncthreads();

    const float* xb = x + (size_t)b*HWN*CCH + g*CG + c;
    float acc = 0.f;
    #pragma unroll
    for (int p = 0; p < 9; p++) {
        float4 w = sw[pl*9 + p];
        int4   o = so[pl*9 + p];
        float v00 = __ldg(xb + o.x);
        float v01 = __ldg(xb + o.y);
        float v10 = __ldg(xb + o.z);
        float v11 = __ldg(xb + o.w);
        acc += v00*w.x + v01*w.y + v10*w.z + v11*w.w;
    }
    out[((size_t)b*HWN + pix0 + pl)*CCH + g*CG + c] = acc;
}

// ---------------- launch ----------------
extern "C" void kernel_launch(void* const* d_in, const int* in_sizes, int n_in,
                              void* d_out, int out_size)
{
    const float* x      = (const float*)d_in[0];
    const float* off_w1 = (const float*)d_in[1];
    const float* off_b1 = (const float*)d_in[2];
    const float* off_w2 = (const float*)d_in[3];
    const float* off_b2 = (const float*)d_in[4];
    const float* mod_w1 = (const float*)d_in[5];
    const float* mod_b1 = (const float*)d_in[6];
    const float* mod_w2 = (const float*)d_in[7];
    const float* mod_b2 = (const float*)d_in[8];
    float* out = (float*)d_out;

    uint32_t *xP, *hP;
    float *mp, *op, *md;
    cudaGetSymbolAddress((void**)&xP, g_xP);
    cudaGetSymbolAddress((void**)&hP, g_hP);
    cudaGetSymbolAddress((void**)&mp, g_mp);
    cudaGetSymbolAddress((void**)&op, g_op);
    cudaGetSymbolAddress((void**)&md, g_mod);

    __nv_bfloat16 *wHi, *wLo;
    cudaGetSymbolAddress((void**)&wHi, g_wHi);
    cudaGetSymbolAddress((void**)&wLo, g_wLo);

    const int SMT4 = 42240 + 4 * (4 * 8 * 80);   // 52480
    const int SMT5 = 42240 + 4 * (5 * 8 * 80);   // 55040
    cudaFuncSetAttribute(conv_mma<4>, cudaFuncAttributeMaxDynamicSharedMemorySize, SMT4);
    cudaFuncSetAttribute(conv_mma<5>, cudaFuncAttributeMaxDynamicSharedMemorySize, SMT5);

    // 1) transpose + pack
    {
        dim3 grid(HWN/32, CCH/32, BSZ), blk(32, 8);
        transpose_kernel<<<grid, blk>>>(x, xP);
    }
    // 2) weight prepack: 25 parts
    // stage1 (rowsPad 32): mod1 k=0..3 x nh=0..1 (8), off1 g=0..3 x nh=0..1 (8)
    // stage2 (rowsPad 40): off2 k=0..3 x nh=0..1 (8), mod2 (1)
    int s1Base[16], s2Base[9];
    {
        PackAll pa;
        int idx = 0, dst = 0;
        for (int k = 0; k < 4; k++)
            for (int nh = 0; nh < 2; nh++) {
                pa.p[idx] = { mod_w1, dst, 256, nh*32, k*64, 32, 32 };
                s1Base[idx] = dst; idx++; dst += 18*32*32;
            }
        for (int g = 0; g < 4; g++)
            for (int nh = 0; nh < 2; nh++) {
                pa.p[idx] = { off_w1, dst, 64, g*64 + nh*32, 0, 32, 32 };
                s1Base[idx] = dst; idx++; dst += 18*32*32;
            }
        int idx2 = 0;
        for (int k = 0; k < 4; k++)
            for (int nh = 0; nh < 2; nh++) {
                pa.p[idx] = { off_w2, dst, 256, nh*40, k*64, nh ? 32 : 40, 40 };
                s2Base[idx2] = dst; idx++; idx2++; dst += 18*40*32;
            }
        pa.p[idx] = { mod_w2, dst, 64, 0, 0, 36, 40 };
        s2Base[idx2] = dst;
        long total = (long)dst + 18*40*32;       // 502272
        prepack_kernel<<<(int)((total + 255)/256), 256>>>(pa);
    }
    // 3) stage 1 (NFR=4, 16 parts): mod1 partials (cin-split x4, n-split x2) + off1 (4 groups x n-split x2)
    {
        ConvArgs a;
        int idx = 0;
        for (int k = 0; k < 4; k++)
            for (int nh = 0; nh < 2; nh++) {
                ConvPart& P = a.p[idx];
                P.in = xP; P.inStride = 0; P.nPart = 1; P.inPacked = 1; P.inAct = 0;
                P.wHi = wHi + s1Base[idx]; P.wLo = wLo + s1Base[idx];
                P.bias = mod_b1 + nh*32; P.out = mp + (size_t)k*MP_STRIDE;
                P.cinTotal = 256; P.ciBase = k*64; P.coutTotal = 64; P.coutBase = nh*32;
                P.CoutValid = 32; P.nCb = 2; P.act = 0; P.outPacked = 0; P.addBias = (k == 0);
                idx++;
            }
        for (int g = 0; g < 4; g++)
            for (int nh = 0; nh < 2; nh++) {
                ConvPart& P = a.p[idx];
                P.in = xP; P.inStride = 0; P.nPart = 1; P.inPacked = 1; P.inAct = 0;
                P.wHi = wHi + s1Base[idx]; P.wLo = wLo + s1Base[idx];
                P.bias = off_b1 + g*64 + nh*32; P.out = hP;
                P.cinTotal = 256; P.ciBase = g*64; P.coutTotal = 256; P.coutBase = g*64 + nh*32;
                P.CoutValid = 32; P.nCb = 2; P.act = 1; P.outPacked = 1; P.addBias = 1;
                idx++;
            }
        conv_mma<4><<<dim3(128, 16), 256, SMT4>>>(a);
    }
    // 4) stage 2 (NFR=5, 9 parts): off2 partials (cin x4, n-split 40/32) + mod2
    {
        ConvArgs a;
        int idx = 0;
        for (int k = 0; k < 4; k++)
            for (int nh = 0; nh < 2; nh++) {
                ConvPart& P = a.p[idx];
                P.in = hP; P.inStride = 0; P.nPart = 1; P.inPacked = 1; P.inAct = 0;
                P.wHi = wHi + s2Base[idx]; P.wLo = wLo + s2Base[idx];
                P.bias = off_b2 + nh*40; P.out = op + (size_t)k*OP_STRIDE;
                P.cinTotal = 256; P.ciBase = k*64; P.coutTotal = 72; P.coutBase = nh*40;
                P.CoutValid = nh ? 32 : 40; P.nCb = 2; P.act = 0; P.outPacked = 0; P.addBias = (k == 0);
                idx++;
            }
        ConvPart& Q = a.p[idx];
        Q.in = mp; Q.inStride = MP_STRIDE; Q.nPart = 4; Q.inPacked = 0; Q.inAct = 1;
        Q.wHi = wHi + s2Base[idx]; Q.wLo = wLo + s2Base[idx];
        Q.bias = mod_b2; Q.out = md;
        Q.cinTotal = 64; Q.ciBase = 0; Q.coutTotal = 36; Q.coutBase = 0;
        Q.CoutValid = 36; Q.nCb = 2; Q.act = 2; Q.outPacked = 0; Q.addBias = 1;
        conv_mma<5><<<dim3(128, 9), 256, SMT5>>>(a);
    }
    // 5) sampling
    {
        dim3 grid(HWN/4, GG, BSZ);
        sample_kernel<<<grid, 256>>>(x, op, md, out);
    }
}

// round 13
// speedup vs baseline: 1.0127x; 1.0127x over previous
#include <cuda_runtime.h>
#include <cuda_bf16.h>
#include <cstdint>

#define BSZ 4
#define CCH 256
#define HH 64
#define WW 64
#define HWN 4096
#define GG 4
#define CG 64

#define MP_STRIDE (BSZ*64*HWN)    // per mod1-partial buffer (floats)
#define OP_STRIDE (BSZ*72*HWN)    // per off2-partial buffer (floats)

// ---------------- warp-MMA helpers ----------------
__device__ __forceinline__ uint32_t smem_u32(const void* p){
  uint32_t a; asm("{ .reg .u64 t; cvta.to.shared.u64 t, %1; cvt.u32.u64 %0, t; }" : "=r"(a) : "l"(p)); return a;
}
__device__ __forceinline__ void ldsm_x4(uint32_t* r, uint32_t a) {
    asm volatile("ldmatrix.sync.aligned.m8n8.x4.shared.b16 {%0,%1,%2,%3}, [%4];"
        : "=r"(r[0]), "=r"(r[1]), "=r"(r[2]), "=r"(r[3]) : "r"(a));
}
__device__ __forceinline__ void ldsm_x2(uint32_t* r, uint32_t a) {
    asm volatile("ldmatrix.sync.aligned.m8n8.x2.shared.b16 {%0,%1}, [%2];"
        : "=r"(r[0]), "=r"(r[1]) : "r"(a));
}
__device__ __forceinline__ void mma_bf16(float* d, const uint32_t* a, uint32_t b0, uint32_t b1) {
    asm volatile("mma.sync.aligned.m16n8k16.row.col.f32.bf16.bf16.f32 "
        "{%0,%1,%2,%3}, {%4,%5,%6,%7}, {%8,%9}, {%0,%1,%2,%3};"
        : "+f"(d[0]), "+f"(d[1]), "+f"(d[2]), "+f"(d[3])
        : "r"(a[0]), "r"(a[1]), "r"(a[2]), "r"(a[3]), "r"(b0), "r"(b1));
}
__device__ __forceinline__ uint32_t pack_hl(float v) {
    __nv_bfloat16 h = __float2bfloat16(v);
    __nv_bfloat16 l = __float2bfloat16(v - __bfloat162float(h));
    return (uint32_t)__bfloat16_as_ushort(h) | ((uint32_t)__bfloat16_as_ushort(l) << 16);
}

// ---------------- scratch ----------------
__device__ uint32_t g_xP[BSZ * CCH * HWN];     // packed bf16 hi/lo of x2d
__device__ uint32_t g_hP[BSZ * CCH * HWN];     // packed off1 output (post-GELU)
__device__ float    g_mp[4 * MP_STRIDE];       // mod1 partials (pre-GELU)
__device__ float    g_op[4 * OP_STRIDE];       // off2 partials
__device__ float    g_mod[BSZ * 36 * HWN];     // mod2 out (post-sigmoid)

// prepacked bf16 hi/lo weights; per part: [chunk=cb*9+tap][rowsPad][32]
#define W_TOTAL 502272
__device__ __nv_bfloat16 g_wHi[W_TOTAL];
__device__ __nv_bfloat16 g_wLo[W_TOTAL];

// ---------------- transpose + bf16-split-pack ----------------
__global__ void transpose_kernel(const float* __restrict__ x, uint32_t* __restrict__ xP) {
    __shared__ float tile[32][33];
    int b  = blockIdx.z;
    int n0 = blockIdx.x * 32;
    int c0 = blockIdx.y * 32;
    int tx = threadIdx.x, ty = threadIdx.y;
    #pragma unroll
    for (int i = ty; i < 32; i += 8)
        tile[i][tx] = x[((size_t)b*HWN + n0 + i)*CCH + c0 + tx];
    __syncthreads();
    #pragma unroll
    for (int i = ty; i < 32; i += 8)
        xP[((size_t)b*CCH + c0 + i)*HWN + n0 + tx] = pack_hl(tile[tx][i]);
}

// ---------------- weight prepack (25 parts) ----------------
struct PackPart { const float* w; int dstBase, wCinG, nInW0, ciInW0, CoutValid, rowsPad; };
struct PackAll  { PackPart p[25]; };

__global__ void prepack_kernel(PackAll a) {
    long e = (long)blockIdx.x * 256 + threadIdx.x;
    int q = 0;
    for (; q < 25; q++) {
        long t = 18L * a.p[q].rowsPad * 32;
        if (e < t) break;
        e -= t;
    }
    if (q >= 25) return;
    PackPart pp = a.p[q];
    int e2 = (int)e;
    int chunk = e2 / (pp.rowsPad * 32);
    int r     = e2 - chunk * (pp.rowsPad * 32);
    int row = r >> 5, j = r & 31;
    int cb = chunk / 9, tap = chunk - cb * 9;
    float v = 0.f;
    if (row < pp.CoutValid)
        v = pp.w[(((size_t)(pp.nInW0 + row)) * pp.wCinG + pp.ciInW0 + cb * 32 + j) * 9 + tap];
    __nv_bfloat16 h = __float2bfloat16(v);
    long dst = pp.dstBase + e;
    g_wHi[dst] = h;
    g_wLo[dst] = __float2bfloat16(v - __bfloat162float(h));
}

// ---------------- implicit-GEMM conv via mma.sync ----------------
struct ConvPart {
    const void* in;
    long inStride; int nPart;
    int inPacked, inAct;
    const __nv_bfloat16 *wHi, *wLo;       // pre-offset to part base
    const float* bias;                     // pre-offset to coutBase
    void* out;
    int cinTotal, ciBase, coutTotal, coutBase, CoutValid, nCb, act, outPacked, addBias;
};
struct ConvArgs { ConvPart p[16]; };

#define SM_A_HI 0
#define SM_A_LO 21120
#define SM_B    42240

template<int NFR>
__device__ __forceinline__ void stage_b(char* smem, const __nv_bfloat16* wHi,
                                        const __nv_bfloat16* wLo, int chunk, int par, int tid) {
    constexpr int BBUF = NFR * 8 * 80;
    const int nv = NFR * 32;
    const uint4* sH = (const uint4*)(wHi + (size_t)chunk * (NFR * 8 * 32));
    const uint4* sL = (const uint4*)(wLo + (size_t)chunk * (NFR * 8 * 32));
    for (int i = tid; i < 2 * nv; i += 256) {
        int arr = (i >= nv);
        int ii  = arr ? i - nv : i;
        uint4 v = arr ? sL[ii] : sH[ii];
        int n = ii >> 2, qq = ii & 3;
        *(uint4*)(smem + SM_B + (size_t)(par * 2 + arr) * BBUF + n * 80 + qq * 16) = v;
    }
}

template<int NFR>
__global__ void __launch_bounds__(256, 4) conv_mma(ConvArgs args) {
    constexpr int BBUF = NFR * 8 * 80;
    extern __shared__ char smem[];
    const ConvPart P = args.p[blockIdx.y];
    const int tid = threadIdx.x;
    const int wid = tid >> 5, lid = tid & 31;
    const int b  = blockIdx.x >> 5;
    const int r0 = (blockIdx.x & 31) << 1;
    uint32_t sb = smem_u32(smem);

    float acc[NFR][4];
    #pragma unroll
    for (int i = 0; i < NFR; i++) { acc[i][0]=acc[i][1]=acc[i][2]=acc[i][3]=0.f; }

    const int m    = wid * 16 + (lid & 15);
    const int yloc = m >> 6, xpix = m & 63;
    const uint32_t aBase  = (uint32_t)(((yloc + 1) * 66 + (xpix + 1)) * 80) + ((lid >> 4) * 16);
    const int nloc4  = (lid & 7) + ((lid >> 4) << 3);
    const int khalfB = ((lid >> 3) & 1) * 16;

    #pragma unroll 1
    for (int cb = 0; cb < P.nCb; cb++) {
        __syncthreads();
        const size_t chBase = ((size_t)(b * P.cinTotal + P.ciBase + cb * 32)) * HWN;
        if (P.inPacked) {
            const uint32_t* ip = (const uint32_t*)P.in + chBase;
            #pragma unroll 1
            for (int i = tid; i < 4 * 66 * 32; i += 256) {
                int j   = i / 264;
                int pix = i - j * 264;
                int py = pix / 66, px = pix - py * 66;
                int y = r0 - 1 + py, x = px - 1;
                uint32_t w = 0;
                if ((unsigned)y < HH && (unsigned)x < WW) w = ip[(size_t)j * HWN + y * WW + x];
                uint32_t o = (uint32_t)(py * 66 + px) * 80 + j * 2;
                *(uint16_t*)(smem + SM_A_HI + o) = (uint16_t)w;
                *(uint16_t*)(smem + SM_A_LO + o) = (uint16_t)(w >> 16);
            }
        } else {
            const float* ip = (const float*)P.in + chBase;
            #pragma unroll 1
            for (int i = tid; i < 4 * 66 * 32; i += 256) {
                int j   = i / 264;
                int pix = i - j * 264;
                int py = pix / 66, px = pix - py * 66;
                int y = r0 - 1 + py, x = px - 1;
                float v = 0.f;
                if ((unsigned)y < HH && (unsigned)x < WW) {
                    size_t idx = (size_t)j * HWN + y * WW + x;
                    v = ip[idx];
                    for (int k = 1; k < P.nPart; k++) v += ip[idx + (size_t)k * P.inStride];
                    if (P.inAct) v = v * normcdff(v);
                }
                __nv_bfloat16 h = __float2bfloat16(v);
                __nv_bfloat16 l = __float2bfloat16(v - __bfloat162float(h));
                uint32_t o = (uint32_t)(py * 66 + px) * 80 + j * 2;
                *(__nv_bfloat16*)(smem + SM_A_HI + o) = h;
                *(__nv_bfloat16*)(smem + SM_A_LO + o) = l;
            }
        }
        stage_b<NFR>(smem, P.wHi, P.wLo, cb * 9, 0, tid);

        #pragma unroll 1
        for (int tap = 0; tap < 9; tap++) {
            __syncthreads();
            if (tap < 8) stage_b<NFR>(smem, P.wHi, P.wLo, cb * 9 + tap + 1, (tap + 1) & 1, tid);
            const int dy = tap / 3 - 1, dx = tap % 3 - 1;
            const uint32_t aOfs  = aBase + (dy * 66 + dx) * 80;
            const uint32_t bBase = sb + SM_B + (uint32_t)((tap & 1) * 2) * BBUF;
            #pragma unroll
            for (int k16 = 0; k16 < 2; k16++) {
                uint32_t ah[4], al[4];
                ldsm_x4(ah, sb + SM_A_HI + aOfs + k16 * 32);
                ldsm_x4(al, sb + SM_A_LO + aOfs + k16 * 32);
                #pragma unroll
                for (int nf2 = 0; nf2 < NFR / 2; nf2++) {
                    uint32_t bAddr = bBase + (uint32_t)(nf2 * 16 + nloc4) * 80 + k16 * 32 + khalfB;
                    uint32_t bh[4], bl[4];
                    ldsm_x4(bh, bAddr);
                    ldsm_x4(bl, bAddr + BBUF);
                    mma_bf16(acc[nf2*2],   ah, bh[0], bh[1]);
                    mma_bf16(acc[nf2*2+1], ah, bh[2], bh[3]);
                    mma_bf16(acc[nf2*2],   al, bh[0], bh[1]);
                    mma_bf16(acc[nf2*2+1], al, bh[2], bh[3]);
                    mma_bf16(acc[nf2*2],   ah, bl[0], bl[1]);
                    mma_bf16(acc[nf2*2+1], ah, bl[2], bl[3]);
                }
                if (NFR & 1) {
                    const int nf = NFR - 1;
                    uint32_t bAddr = bBase + (uint32_t)(nf * 8 + (lid & 7)) * 80 + k16 * 32 + khalfB;
                    uint32_t bh[2], bl[2];
                    ldsm_x2(bh, bAddr);
                    ldsm_x2(bl, bAddr + BBUF);
                    mma_bf16(acc[nf], ah, bh[0], bh[1]);
                    mma_bf16(acc[nf], al, bh[0], bh[1]);
                    mma_bf16(acc[nf], ah, bl[0], bl[1]);
                }
            }
        }
    }

    // epilogue via smem transpose for coalesced stores
    __syncthreads();
    float* sd = (float*)smem;
    {
        const int rr = lid >> 2, cc = (lid & 3) * 2;
        const int mB = wid * 16;
        #pragma unroll
        for (int nf = 0; nf < NFR; nf++) {
            int n = nf * 8 + cc;
            sd[(n    ) * 132 + mB + rr    ] = acc[nf][0];
            sd[(n + 1) * 132 + mB + rr    ] = acc[nf][1];
            sd[(n    ) * 132 + mB + rr + 8] = acc[nf][2];
            sd[(n + 1) * 132 + mB + rr + 8] = acc[nf][3];
        }
    }
    __syncthreads();
    const int pixBase = r0 * WW;
    for (int i = tid; i < P.CoutValid * 128; i += 256) {
        int n = i >> 7, mm = i & 127;
        float v = sd[n * 132 + mm] + (P.addBias ? P.bias[n] : 0.f);
        if (P.act == 1)      v = v * normcdff(v);
        else if (P.act == 2) v = 1.f / (1.f + expf(-v));
        size_t oidx = ((size_t)(b * P.coutTotal + P.coutBase + n)) * HWN + pixBase + mm;
        if (P.outPacked) ((uint32_t*)P.out)[oidx] = pack_hl(v);
        else             ((float*)P.out)[oidx] = v;
    }
}

// ---------------- deformable sampling (sums 4 off partials) ----------------
__global__ void __launch_bounds__(256) sample_kernel(
    const float* __restrict__ x,
    const float* __restrict__ op,
    const float* __restrict__ mod,
    float* __restrict__ out)
{
    __shared__ float4 sw[36];
    __shared__ int4   so[36];

    const int t    = threadIdx.x;
    const int c    = t & 63;
    const int pl   = t >> 6;
    const int pix0 = blockIdx.x * 4;
    const int g    = blockIdx.y;
    const int b    = blockIdx.z;

    if (t < 36) {
        const int pli = t / 9;
        const int p   = t - pli * 9;
        const int pix = pix0 + pli;
        const int yq  = pix >> 6;
        const int xq  = pix & 63;

        const float* offp = op  + ((size_t)b*72 + g*18)*HWN + pix;
        const float* modp = mod + ((size_t)b*36 + g*9 )*HWN + pix;

        float ox = 0.f, oy = 0.f;
        #pragma unroll
        for (int k = 0; k < 4; k++) {
            ox += offp[(size_t)k*OP_STRIDE + (size_t)p*HWN];
            oy += offp[(size_t)k*OP_STRIDE + (size_t)(9+p)*HWN];
        }
        float mv = modp[(size_t)p*HWN] * (1.f/9.f);

        float px = fminf(fmaxf((float)(xq + (p%3) - 1) + ox, 0.f), (float)(WW-1));
        float py = fminf(fmaxf((float)(yq + (p/3) - 1) + oy, 0.f), (float)(HH-1));

        float x0f = floorf(px), y0f = floorf(py);
        float wx = px - x0f, wy = py - y0f;
        int x0 = (int)x0f, y0 = (int)y0f;
        int x1 = min(x0 + 1, WW-1);
        int y1 = min(y0 + 1, HH-1);

        sw[t] = make_float4((1.f-wx)*(1.f-wy)*mv, wx*(1.f-wy)*mv,
                            (1.f-wx)*wy*mv,       wx*wy*mv);
        so[t] = make_int4((y0*WW + x0)*CCH, (y0*WW + x1)*CCH,
                          (y1*WW + x0)*CCH, (y1*WW + x1)*CCH);
    }
    __syncthreads();

    const float* xb = x + (size_t)b*HWN*CCH + g*CG + c;
    float acc = 0.f;
    #pragma unroll
    for (int p = 0; p < 9; p++) {
        float4 w = sw[pl*9 + p];
        int4   o = so[pl*9 + p];
        float v00 = __ldg(xb + o.x);
        float v01 = __ldg(xb + o.y);
        float v10 = __ldg(xb + o.z);
        float v11 = __ldg(xb + o.w);
        acc += v00*w.x + v01*w.y + v10*w.z + v11*w.w;
    }
    out[((size_t)b*HWN + pix0 + pl)*CCH + g*CG + c] = acc;
}

// ---------------- launch ----------------
extern "C" void kernel_launch(void* const* d_in, const int* in_sizes, int n_in,
                              void* d_out, int out_size)
{
    const float* x      = (const float*)d_in[0];
    const float* off_w1 = (const float*)d_in[1];
    const float* off_b1 = (const float*)d_in[2];
    const float* off_w2 = (const float*)d_in[3];
    const float* off_b2 = (const float*)d_in[4];
    const float* mod_w1 = (const float*)d_in[5];
    const float* mod_b1 = (const float*)d_in[6];
    const float* mod_w2 = (const float*)d_in[7];
    const float* mod_b2 = (const float*)d_in[8];
    float* out = (float*)d_out;

    uint32_t *xP, *hP;
    float *mp, *op, *md;
    cudaGetSymbolAddress((void**)&xP, g_xP);
    cudaGetSymbolAddress((void**)&hP, g_hP);
    cudaGetSymbolAddress((void**)&mp, g_mp);
    cudaGetSymbolAddress((void**)&op, g_op);
    cudaGetSymbolAddress((void**)&md, g_mod);

    __nv_bfloat16 *wHi, *wLo;
    cudaGetSymbolAddress((void**)&wHi, g_wHi);
    cudaGetSymbolAddress((void**)&wLo, g_wLo);

    const int SMT4 = 42240 + 4 * (4 * 8 * 80);   // 52480
    const int SMT5 = 42240 + 4 * (5 * 8 * 80);   // 55040
    cudaFuncSetAttribute(conv_mma<4>, cudaFuncAttributeMaxDynamicSharedMemorySize, SMT4);
    cudaFuncSetAttribute(conv_mma<5>, cudaFuncAttributeMaxDynamicSharedMemorySize, SMT5);

    // 1) transpose + pack
    {
        dim3 grid(HWN/32, CCH/32, BSZ), blk(32, 8);
        transpose_kernel<<<grid, blk>>>(x, xP);
    }
    // 2) weight prepack: 25 parts
    // stage1 (rowsPad 32): mod1 k=0..3 x nh=0..1 (8), off1 g=0..3 x nh=0..1 (8)
    // stage2 (rowsPad 40): off2 k=0..3 x nh=0..1 (8), mod2 (1)
    int s1Base[16], s2Base[9];
    {
        PackAll pa;
        int idx = 0, dst = 0;
        for (int k = 0; k < 4; k++)
            for (int nh = 0; nh < 2; nh++) {
                pa.p[idx] = { mod_w1, dst, 256, nh*32, k*64, 32, 32 };
                s1Base[idx] = dst; idx++; dst += 18*32*32;
            }
        for (int g = 0; g < 4; g++)
            for (int nh = 0; nh < 2; nh++) {
                pa.p[idx] = { off_w1, dst, 64, g*64 + nh*32, 0, 32, 32 };
                s1Base[idx] = dst; idx++; dst += 18*32*32;
            }
        int idx2 = 0;
        for (int k = 0; k < 4; k++)
            for (int nh = 0; nh < 2; nh++) {
                pa.p[idx] = { off_w2, dst, 256, nh*40, k*64, nh ? 32 : 40, 40 };
                s2Base[idx2] = dst; idx++; idx2++; dst += 18*40*32;
            }
        pa.p[idx] = { mod_w2, dst, 64, 0, 0, 36, 40 };
        s2Base[idx2] = dst;
        long total = (long)dst + 18*40*32;       // 502272
        prepack_kernel<<<(int)((total + 255)/256), 256>>>(pa);
    }
    // 3) stage 1 (NFR=4, 16 parts): mod1 partials (cin-split x4, n-split x2) + off1 (4 groups x n-split x2)
    {
        ConvArgs a;
        int idx = 0;
        for (int k = 0; k < 4; k++)
            for (int nh = 0; nh < 2; nh++) {
                ConvPart& P = a.p[idx];
                P.in = xP; P.inStride = 0; P.nPart = 1; P.inPacked = 1; P.inAct = 0;
                P.wHi = wHi + s1Base[idx]; P.wLo = wLo + s1Base[idx];
                P.bias = mod_b1 + nh*32; P.out = mp + (size_t)k*MP_STRIDE;
                P.cinTotal = 256; P.ciBase = k*64; P.coutTotal = 64; P.coutBase = nh*32;
                P.CoutValid = 32; P.nCb = 2; P.act = 0; P.outPacked = 0; P.addBias = (k == 0);
                idx++;
            }
        for (int g = 0; g < 4; g++)
            for (int nh = 0; nh < 2; nh++) {
                ConvPart& P = a.p[idx];
                P.in = xP; P.inStride = 0; P.nPart = 1; P.inPacked = 1; P.inAct = 0;
                P.wHi = wHi + s1Base[idx]; P.wLo = wLo + s1Base[idx];
                P.bias = off_b1 + g*64 + nh*32; P.out = hP;
                P.cinTotal = 256; P.ciBase = g*64; P.coutTotal = 256; P.coutBase = g*64 + nh*32;
                P.CoutValid = 32; P.nCb = 2; P.act = 1; P.outPacked = 1; P.addBias = 1;
                idx++;
            }
        conv_mma<4><<<dim3(128, 16), 256, SMT4>>>(a);
    }
    // 4) stage 2 (NFR=5, 9 parts): off2 partials (cin x4, n-split 40/32) + mod2
    {
        ConvArgs a;
        int idx = 0;
        for (int k = 0; k < 4; k++)
            for (int nh = 0; nh < 2; nh++) {
                ConvPart& P = a.p[idx];
                P.in = hP; P.inStride = 0; P.nPart = 1; P.inPacked = 1; P.inAct = 0;
                P.wHi = wHi + s2Base[idx]; P.wLo = wLo + s2Base[idx];
                P.bias = off_b2 + nh*40; P.out = op + (size_t)k*OP_STRIDE;
                P.cinTotal = 256; P.ciBase = k*64; P.coutTotal = 72; P.coutBase = nh*40;
                P.CoutValid = nh ? 32 : 40; P.nCb = 2; P.act = 0; P.outPacked = 0; P.addBias = (k == 0);
                idx++;
            }
        ConvPart& Q = a.p[idx];
        Q.in = mp; Q.inStride = MP_STRIDE; Q.nPart = 4; Q.inPacked = 0; Q.inAct = 1;
        Q.wHi = wHi + s2Base[idx]; Q.wLo = wLo + s2Base[idx];
        Q.bias = mod_b2; Q.out = md;
        Q.cinTotal = 64; Q.ciBase = 0; Q.coutTotal = 36; Q.coutBase = 0;
        Q.CoutValid = 36; Q.nCb = 2; Q.act = 2; Q.outPacked = 0; Q.addBias = 1;
        conv_mma<5><<<dim3(128, 9), 256, SMT5>>>(a);
    }
    // 5) sampling
    {
        dim3 grid(HWN/4, GG, BSZ);
        sample_kernel<<<grid, 256>>>(x, op, md, out);
    }
}

// round 14
// speedup vs baseline: 1.2514x; 1.2357x over previous
#include <cuda_runtime.h>
#include <cuda_bf16.h>
#include <cstdint>

#define BSZ 4
#define CCH 256
#define HH 64
#define WW 64
#define HWN 4096
#define GG 4
#define CG 64

#define MP_STRIDE (BSZ*64*HWN)    // per mod1-partial buffer (floats)
#define OP_STRIDE (BSZ*72*HWN)    // per off2-partial buffer (floats)

// ---------------- warp-MMA / async helpers ----------------
__device__ __forceinline__ uint32_t smem_u32(const void* p){
  uint32_t a; asm("{ .reg .u64 t; cvta.to.shared.u64 t, %1; cvt.u32.u64 %0, t; }" : "=r"(a) : "l"(p)); return a;
}
__device__ __forceinline__ void ldsm_x4(uint32_t* r, uint32_t a) {
    asm volatile("ldmatrix.sync.aligned.m8n8.x4.shared.b16 {%0,%1,%2,%3}, [%4];"
        : "=r"(r[0]), "=r"(r[1]), "=r"(r[2]), "=r"(r[3]) : "r"(a));
}
__device__ __forceinline__ void ldsm_x2(uint32_t* r, uint32_t a) {
    asm volatile("ldmatrix.sync.aligned.m8n8.x2.shared.b16 {%0,%1}, [%2];"
        : "=r"(r[0]), "=r"(r[1]) : "r"(a));
}
__device__ __forceinline__ void mma_bf16(float* d, const uint32_t* a, uint32_t b0, uint32_t b1) {
    asm volatile("mma.sync.aligned.m16n8k16.row.col.f32.bf16.bf16.f32 "
        "{%0,%1,%2,%3}, {%4,%5,%6,%7}, {%8,%9}, {%0,%1,%2,%3};"
        : "+f"(d[0]), "+f"(d[1]), "+f"(d[2]), "+f"(d[3])
        : "r"(a[0]), "r"(a[1]), "r"(a[2]), "r"(a[3]), "r"(b0), "r"(b1));
}
__device__ __forceinline__ void cp16(uint32_t dst, const void* src) {
    asm volatile("cp.async.cg.shared.global [%0], [%1], 16;" :: "r"(dst), "l"(src));
}
#define CP_COMMIT() asm volatile("cp.async.commit_group;" ::: "memory")
#define CP_WAIT0()  asm volatile("cp.async.wait_group 0;" ::: "memory")

__device__ __forceinline__ uint32_t pack_hl(float v) {
    __nv_bfloat16 h = __float2bfloat16(v);
    __nv_bfloat16 l = __float2bfloat16(v - __bfloat162float(h));
    return (uint32_t)__bfloat16_as_ushort(h) | ((uint32_t)__bfloat16_as_ushort(l) << 16);
}

// ---------------- scratch ----------------
__device__ uint32_t g_xP[BSZ * CCH * HWN];     // packed bf16 hi/lo of x2d
__device__ uint32_t g_hP[BSZ * CCH * HWN];     // packed off1 output (post-GELU)
__device__ float    g_mp[4 * MP_STRIDE];       // mod1 partials (pre-GELU)
__device__ float    g_op[4 * OP_STRIDE];       // off2 partials
__device__ float    g_mod[BSZ * 36 * HWN];     // mod2 out (post-sigmoid)

// prepacked bf16 hi/lo weights; per part: [chunk=cb*9+tap][rowsPad][32]
#define W_TOTAL 502272
__device__ __nv_bfloat16 g_wHi[W_TOTAL];
__device__ __nv_bfloat16 g_wLo[W_TOTAL];

// ---------------- transpose + bf16-split-pack ----------------
__global__ void transpose_kernel(const float* __restrict__ x, uint32_t* __restrict__ xP) {
    __shared__ float tile[32][33];
    int b  = blockIdx.z;
    int n0 = blockIdx.x * 32;
    int c0 = blockIdx.y * 32;
    int tx = threadIdx.x, ty = threadIdx.y;
    #pragma unroll
    for (int i = ty; i < 32; i += 8)
        tile[i][tx] = x[((size_t)b*HWN + n0 + i)*CCH + c0 + tx];
    __syncthreads();
    #pragma unroll
    for (int i = ty; i < 32; i += 8)
        xP[((size_t)b*CCH + c0 + i)*HWN + n0 + tx] = pack_hl(tile[tx][i]);
}

// ---------------- weight prepack (25 parts) ----------------
struct PackPart { const float* w; int dstBase, wCinG, nInW0, ciInW0, CoutValid, rowsPad; };
struct PackAll  { PackPart p[25]; };

__global__ void prepack_kernel(PackAll a) {
    long e = (long)blockIdx.x * 256 + threadIdx.x;
    int q = 0;
    for (; q < 25; q++) {
        long t = 18L * a.p[q].rowsPad * 32;
        if (e < t) break;
        e -= t;
    }
    if (q >= 25) return;
    PackPart pp = a.p[q];
    int e2 = (int)e;
    int chunk = e2 / (pp.rowsPad * 32);
    int r     = e2 - chunk * (pp.rowsPad * 32);
    int row = r >> 5, j = r & 31;
    int cb = chunk / 9, tap = chunk - cb * 9;
    float v = 0.f;
    if (row < pp.CoutValid)
        v = pp.w[(((size_t)(pp.nInW0 + row)) * pp.wCinG + pp.ciInW0 + cb * 32 + j) * 9 + tap];
    __nv_bfloat16 h = __float2bfloat16(v);
    long dst = pp.dstBase + e;
    g_wHi[dst] = h;
    g_wLo[dst] = __float2bfloat16(v - __bfloat162float(h));
}

// ---------------- implicit-GEMM conv via mma.sync ----------------
struct ConvPart {
    const void* in;
    long inStride; int nPart;
    int inPacked, inAct;
    const __nv_bfloat16 *wHi, *wLo;       // pre-offset to part base
    const float* bias;                     // pre-offset to coutBase
    void* out;
    int cinTotal, ciBase, coutTotal, coutBase, CoutValid, nCb, act, outPacked, addBias;
};
struct ConvArgs { ConvPart p[16]; };

#define SM_A_HI 0
#define SM_A_LO 21120
#define SM_B    42240

// async-stage one B chunk (hi+lo) into parity buffer 'par'
template<int NFR>
__device__ __forceinline__ void stage_b_async(char* smem_c, uint32_t sb,
        const __nv_bfloat16* wHi, const __nv_bfloat16* wLo, int chunk, int par, int tid) {
    constexpr int NV   = NFR * 32;        // uint4 per array
    constexpr int BBUF = NFR * 8 * 80;
    const char* gH = (const char*)(wHi + (size_t)chunk * (NFR*8*32));
    const char* gL = (const char*)(wLo + (size_t)chunk * (NFR*8*32));
    #pragma unroll
    for (int r = 0; r < (2*NV + 255)/256; r++) {
        int i = tid + r*256;
        if ((2*NV % 256 == 0) || i < 2*NV) {
            int arr = (i >= NV);
            int ii  = i - (arr ? NV : 0);
            uint32_t dst = sb + SM_B + (uint32_t)(par*2 + arr)*BBUF + (ii>>2)*80 + (ii&3)*16;
            const char* src = (arr ? gL : gH) + ii*16;
            cp16(dst, src);
        }
    }
}

template<int NFR>
__global__ void __launch_bounds__(256, 4) conv_mma(ConvArgs args) {
    constexpr int BBUF = NFR * 8 * 80;
    extern __shared__ char smem[];
    const ConvPart P = args.p[blockIdx.y];
    const int tid = threadIdx.x;
    const int wid = tid >> 5, lid = tid & 31;
    const int b  = blockIdx.x >> 5;
    const int r0 = (blockIdx.x & 31) << 1;
    uint32_t sb = smem_u32(smem);

    float acc[NFR][4];
    #pragma unroll
    for (int i = 0; i < NFR; i++) { acc[i][0]=acc[i][1]=acc[i][2]=acc[i][3]=0.f; }

    const int m    = wid * 16 + (lid & 15);
    const int yloc = m >> 6, xpix = m & 63;
    const uint32_t aBase  = (uint32_t)(((yloc + 1) * 66 + (xpix + 1)) * 80) + ((lid >> 4) * 16);
    const int nloc4  = (lid & 7) + ((lid >> 4) << 3);
    const int khalfB = ((lid >> 3) & 1) * 16;

    // one-time: zero border columns px=0 and px=65 (x=-1 and x=64 are always OOB)
    {
        int pr = tid >> 5;            // 0..7
        int j  = tid & 31;
        int py = pr >> 1, px = (pr & 1) * 65;
        uint32_t o = (uint32_t)(py*66 + px) * 80 + j*2;
        *(uint16_t*)(smem + SM_A_HI + o) = 0;
        *(uint16_t*)(smem + SM_A_LO + o) = 0;
    }
    __syncthreads();

    #pragma unroll 1
    for (int cb = 0; cb < P.nCb; cb++) {
        const size_t chBase = ((size_t)(b * P.cinTotal + P.ciBase + cb * 32)) * HWN;
        // ---- stage A patch ----
        if (P.inPacked) {
            // divide-free, batched: j = channel, 8 lanes sweep 32 pixel-pairs/row
            const uint32_t* ip = (const uint32_t*)P.in + chBase;
            const int j = tid >> 3;
            const int lane8 = tid & 7;
            const uint32_t* cp = ip + (size_t)j * HWN;
            #pragma unroll
            for (int py = 0; py < 4; py++) {
                int y = r0 - 1 + py;
                bool vy = ((unsigned)y < HH);
                const uint32_t* rp = cp + y * WW;
                #pragma unroll
                for (int it = 0; it < 4; it++) {
                    int p = lane8 + it * 8;          // pair 0..31
                    uint2 v = make_uint2(0u, 0u);
                    if (vy) v = *(const uint2*)(rp + 2*p);
                    uint32_t o = (uint32_t)(py*66 + 1 + 2*p) * 80 + j*2;
                    *(uint16_t*)(smem + SM_A_HI + o)      = (uint16_t)v.x;
                    *(uint16_t*)(smem + SM_A_LO + o)      = (uint16_t)(v.x >> 16);
                    *(uint16_t*)(smem + SM_A_HI + o + 80) = (uint16_t)v.y;
                    *(uint16_t*)(smem + SM_A_LO + o + 80) = (uint16_t)(v.y >> 16);
                }
            }
        } else {
            const float* ip = (const float*)P.in + chBase;
            for (int i = tid; i < 4 * 66 * 32; i += 256) {
                int j   = i / 264;
                int pix = i - j * 264;
                int py = pix / 66, px = pix - py * 66;
                int y = r0 - 1 + py, x = px - 1;
                float v = 0.f;
                if ((unsigned)y < HH && (unsigned)x < WW) {
                    size_t idx = (size_t)j * HWN + y * WW + x;
                    v = ip[idx];
                    for (int k = 1; k < P.nPart; k++) v += ip[idx + (size_t)k * P.inStride];
                    if (P.inAct) v = v * normcdff(v);
                }
                __nv_bfloat16 h = __float2bfloat16(v);
                __nv_bfloat16 l = __float2bfloat16(v - __bfloat162float(h));
                uint32_t o = (uint32_t)(py * 66 + px) * 80 + j * 2;
                *(__nv_bfloat16*)(smem + SM_A_HI + o) = h;
                *(__nv_bfloat16*)(smem + SM_A_LO + o) = l;
            }
        }
        // ---- stage B chunk 0 (async) ----
        stage_b_async<NFR>(smem, sb, P.wHi, P.wLo, cb*9, 0, tid);
        CP_COMMIT();
        CP_WAIT0();
        __syncthreads();

        #pragma unroll 1
        for (int tap = 0; tap < 9; tap++) {
            if (tap < 8) {
                stage_b_async<NFR>(smem, sb, P.wHi, P.wLo, cb*9 + tap + 1, (tap + 1) & 1, tid);
                CP_COMMIT();
            }
            const int dy = tap / 3 - 1, dx = tap % 3 - 1;
            const uint32_t aOfs  = aBase + (dy * 66 + dx) * 80;
            const uint32_t bBase = sb + SM_B + (uint32_t)((tap & 1) * 2) * BBUF;
            #pragma unroll
            for (int k16 = 0; k16 < 2; k16++) {
                uint32_t ah[4], al[4];
                ldsm_x4(ah, sb + SM_A_HI + aOfs + k16 * 32);
                ldsm_x4(al, sb + SM_A_LO + aOfs + k16 * 32);
                #pragma unroll
                for (int nf2 = 0; nf2 < NFR / 2; nf2++) {
                    uint32_t bAddr = bBase + (uint32_t)(nf2 * 16 + nloc4) * 80 + k16 * 32 + khalfB;
                    uint32_t bh[4], bl[4];
                    ldsm_x4(bh, bAddr);
                    ldsm_x4(bl, bAddr + BBUF);
                    mma_bf16(acc[nf2*2],   ah, bh[0], bh[1]);
                    mma_bf16(acc[nf2*2+1], ah, bh[2], bh[3]);
                    mma_bf16(acc[nf2*2],   al, bh[0], bh[1]);
                    mma_bf16(acc[nf2*2+1], al, bh[2], bh[3]);
                    mma_bf16(acc[nf2*2],   ah, bl[0], bl[1]);
                    mma_bf16(acc[nf2*2+1], ah, bl[2], bl[3]);
                }
                if (NFR & 1) {
                    const int nf = NFR - 1;
                    uint32_t bAddr = bBase + (uint32_t)(nf * 8 + (lid & 7)) * 80 + k16 * 32 + khalfB;
                    uint32_t bh[2], bl[2];
                    ldsm_x2(bh, bAddr);
                    ldsm_x2(bl, bAddr + BBUF);
                    mma_bf16(acc[nf], ah, bh[0], bh[1]);
                    mma_bf16(acc[nf], al, bh[0], bh[1]);
                    mma_bf16(acc[nf], ah, bl[0], bl[1]);
                }
            }
            if (tap < 8) CP_WAIT0();
            __syncthreads();
        }
    }

    // epilogue via smem transpose for coalesced stores
    float* sd = (float*)smem;
    {
        const int rr = lid >> 2, cc = (lid & 3) * 2;
        const int mB = wid * 16;
        #pragma unroll
        for (int nf = 0; nf < NFR; nf++) {
            int n = nf * 8 + cc;
            sd[(n    ) * 132 + mB + rr    ] = acc[nf][0];
            sd[(n + 1) * 132 + mB + rr    ] = acc[nf][1];
            sd[(n    ) * 132 + mB + rr + 8] = acc[nf][2];
            sd[(n + 1) * 132 + mB + rr + 8] = acc[nf][3];
        }
    }
    __syncthreads();
    const int pixBase = r0 * WW;
    for (int i = tid; i < P.CoutValid * 128; i += 256) {
        int n = i >> 7, mm = i & 127;
        float v = sd[n * 132 + mm] + (P.addBias ? P.bias[n] : 0.f);
        if (P.act == 1)      v = v * normcdff(v);
        else if (P.act == 2) v = 1.f / (1.f + expf(-v));
        size_t oidx = ((size_t)(b * P.coutTotal + P.coutBase + n)) * HWN + pixBase + mm;
        if (P.outPacked) ((uint32_t*)P.out)[oidx] = pack_hl(v);
        else             ((float*)P.out)[oidx] = v;
    }
}

// ---------------- deformable sampling (sums 4 off partials) ----------------
__global__ void __launch_bounds__(256) sample_kernel(
    const float* __restrict__ x,
    const float* __restrict__ op,
    const float* __restrict__ mod,
    float* __restrict__ out)
{
    __shared__ float4 sw[36];
    __shared__ int4   so[36];

    const int t    = threadIdx.x;
    const int c    = t & 63;
    const int pl   = t >> 6;
    const int pix0 = blockIdx.x * 4;
    const int g    = blockIdx.y;
    const int b    = blockIdx.z;

    if (t < 36) {
        const int pli = t / 9;
        const int p   = t - pli * 9;
        const int pix = pix0 + pli;
        const int yq  = pix >> 6;
        const int xq  = pix & 63;

        const float* offp = op  + ((size_t)b*72 + g*18)*HWN + pix;
        const float* modp = mod + ((size_t)b*36 + g*9 )*HWN + pix;

        float ox = 0.f, oy = 0.f;
        #pragma unroll
        for (int k = 0; k < 4; k++) {
            ox += offp[(size_t)k*OP_STRIDE + (size_t)p*HWN];
            oy += offp[(size_t)k*OP_STRIDE + (size_t)(9+p)*HWN];
        }
        float mv = modp[(size_t)p*HWN] * (1.f/9.f);

        float px = fminf(fmaxf((float)(xq + (p%3) - 1) + ox, 0.f), (float)(WW-1));
        float py = fminf(fmaxf((float)(yq + (p/3) - 1) + oy, 0.f), (float)(HH-1));

        float x0f = floorf(px), y0f = floorf(py);
        float wx = px - x0f, wy = py - y0f;
        int x0 = (int)x0f, y0 = (int)y0f;
        int x1 = min(x0 + 1, WW-1);
        int y1 = min(y0 + 1, HH-1);

        sw[t] = make_float4((1.f-wx)*(1.f-wy)*mv, wx*(1.f-wy)*mv,
                            (1.f-wx)*wy*mv,       wx*wy*mv);
        so[t] = make_int4((y0*WW + x0)*CCH, (y0*WW + x1)*CCH,
                          (y1*WW + x0)*CCH, (y1*WW + x1)*CCH);
    }
    __syncthreads();

    const float* xb = x + (size_t)b*HWN*CCH + g*CG + c;
    float acc = 0.f;
    #pragma unroll
    for (int p = 0; p < 9; p++) {
        float4 w = sw[pl*9 + p];
        int4   o = so[pl*9 + p];
        float v00 = __ldg(xb + o.x);
        float v01 = __ldg(xb + o.y);
        float v10 = __ldg(xb + o.z);
        float v11 = __ldg(xb + o.w);
        acc += v00*w.x + v01*w.y + v10*w.z + v11*w.w;
    }
    out[((size_t)b*HWN + pix0 + pl)*CCH + g*CG + c] = acc;
}

// ---------------- launch ----------------
extern "C" void kernel_launch(void* const* d_in, const int* in_sizes, int n_in,
                              void* d_out, int out_size)
{
    const float* x      = (const float*)d_in[0];
    const float* off_w1 = (const float*)d_in[1];
    const float* off_b1 = (const float*)d_in[2];
    const float* off_w2 = (const float*)d_in[3];
    const float* off_b2 = (const float*)d_in[4];
    const float* mod_w1 = (const float*)d_in[5];
    const float* mod_b1 = (const float*)d_in[6];
    const float* mod_w2 = (const float*)d_in[7];
    const float* mod_b2 = (const float*)d_in[8];
    float* out = (float*)d_out;

    uint32_t *xP, *hP;
    float *mp, *op, *md;
    cudaGetSymbolAddress((void**)&xP, g_xP);
    cudaGetSymbolAddress((void**)&hP, g_hP);
    cudaGetSymbolAddress((void**)&mp, g_mp);
    cudaGetSymbolAddress((void**)&op, g_op);
    cudaGetSymbolAddress((void**)&md, g_mod);

    __nv_bfloat16 *wHi, *wLo;
    cudaGetSymbolAddress((void**)&wHi, g_wHi);
    cudaGetSymbolAddress((void**)&wLo, g_wLo);

    const int SMT4 = 42240 + 4 * (4 * 8 * 80);   // 52480
    const int SMT5 = 42240 + 4 * (5 * 8 * 80);   // 55040
    cudaFuncSetAttribute(conv_mma<4>, cudaFuncAttributeMaxDynamicSharedMemorySize, SMT4);
    cudaFuncSetAttribute(conv_mma<5>, cudaFuncAttributeMaxDynamicSharedMemorySize, SMT5);

    // 1) transpose + pack
    {
        dim3 grid(HWN/32, CCH/32, BSZ), blk(32, 8);
        transpose_kernel<<<grid, blk>>>(x, xP);
    }
    // 2) weight prepack: 25 parts
    int s1Base[16], s2Base[9];
    {
        PackAll pa;
        int idx = 0, dst = 0;
        for (int k = 0; k < 4; k++)
            for (int nh = 0; nh < 2; nh++) {
                pa.p[idx] = { mod_w1, dst, 256, nh*32, k*64, 32, 32 };
                s1Base[idx] = dst; idx++; dst += 18*32*32;
            }
        for (int g = 0; g < 4; g++)
            for (int nh = 0; nh < 2; nh++) {
                pa.p[idx] = { off_w1, dst, 64, g*64 + nh*32, 0, 32, 32 };
                s1Base[idx] = dst; idx++; dst += 18*32*32;
            }
        int idx2 = 0;
        for (int k = 0; k < 4; k++)
            for (int nh = 0; nh < 2; nh++) {
                pa.p[idx] = { off_w2, dst, 256, nh*40, k*64, nh ? 32 : 40, 40 };
                s2Base[idx2] = dst; idx++; idx2++; dst += 18*40*32;
            }
        pa.p[idx] = { mod_w2, dst, 64, 0, 0, 36, 40 };
        s2Base[idx2] = dst;
        long total = (long)dst + 18*40*32;       // 502272
        prepack_kernel<<<(int)((total + 255)/256), 256>>>(pa);
    }
    // 3) stage 1 (NFR=4, 16 parts)
    {
        ConvArgs a;
        int idx = 0;
        for (int k = 0; k < 4; k++)
            for (int nh = 0; nh < 2; nh++) {
                ConvPart& P = a.p[idx];
                P.in = xP; P.inStride = 0; P.nPart = 1; P.inPacked = 1; P.inAct = 0;
                P.wHi = wHi + s1Base[idx]; P.wLo = wLo + s1Base[idx];
                P.bias = mod_b1 + nh*32; P.out = mp + (size_t)k*MP_STRIDE;
                P.cinTotal = 256; P.ciBase = k*64; P.coutTotal = 64; P.coutBase = nh*32;
                P.CoutValid = 32; P.nCb = 2; P.act = 0; P.outPacked = 0; P.addBias = (k == 0);
                idx++;
            }
        for (int g = 0; g < 4; g++)
            for (int nh = 0; nh < 2; nh++) {
                ConvPart& P = a.p[idx];
                P.in = xP; P.inStride = 0; P.nPart = 1; P.inPacked = 1; P.inAct = 0;
                P.wHi = wHi + s1Base[idx]; P.wLo = wLo + s1Base[idx];
                P.bias = off_b1 + g*64 + nh*32; P.out = hP;
                P.cinTotal = 256; P.ciBase = g*64; P.coutTotal = 256; P.coutBase = g*64 + nh*32;
                P.CoutValid = 32; P.nCb = 2; P.act = 1; P.outPacked = 1; P.addBias = 1;
                idx++;
            }
        conv_mma<4><<<dim3(128, 16), 256, SMT4>>>(a);
    }
    // 4) stage 2 (NFR=5, 9 parts)
    {
        ConvArgs a;
        int idx = 0;
        for (int k = 0; k < 4; k++)
            for (int nh = 0; nh < 2; nh++) {
                ConvPart& P = a.p[idx];
                P.in = hP; P.inStride = 0; P.nPart = 1; P.inPacked = 1; P.inAct = 0;
                P.wHi = wHi + s2Base[idx]; P.wLo = wLo + s2Base[idx];
                P.bias = off_b2 + nh*40; P.out = op + (size_t)k*OP_STRIDE;
                P.cinTotal = 256; P.ciBase = k*64; P.coutTotal = 72; P.coutBase = nh*40;
                P.CoutValid = nh ? 32 : 40; P.nCb = 2; P.act = 0; P.outPacked = 0; P.addBias = (k == 0);
                idx++;
            }
        ConvPart& Q = a.p[idx];
        Q.in = mp; Q.inStride = MP_STRIDE; Q.nPart = 4; Q.inPacked = 0; Q.inAct = 1;
        Q.wHi = wHi + s2Base[idx]; Q.wLo = wLo + s2Base[idx];
        Q.bias = mod_b2; Q.out = md;
        Q.cinTotal = 64; Q.ciBase = 0; Q.coutTotal = 36; Q.coutBase = 0;
        Q.CoutValid = 36; Q.nCb = 2; Q.act = 2; Q.outPacked = 0; Q.addBias = 1;
        conv_mma<5><<<dim3(128, 9), 256, SMT5>>>(a);
    }
    // 5) sampling
    {
        dim3 grid(HWN/4, GG, BSZ);
        sample_kernel<<<grid, 256>>>(x, op, md, out);
    }
}